// round 15
// baseline (speedup 1.0000x reference)
#include <cuda_runtime.h>

#define NN 10000
#define NB 32
#define NE 320000
#define XS (NN*8)       // 80000 floats per batch
#define MAXDEG 128

// ---------------- device scratch ----------------
__device__ __align__(128) int       g_counts[NN];
__device__ __align__(128) long long g_edge[NN * MAXDEG];   // (perm<<32)|col
__device__ __align__(128) float     g_xc[NN * NB * 8];     // xc[c][b*8+i], 1KB/node

// ---------------- helpers ----------------
union F4 { float4 f; ulonglong2 u; };
union U64F2 { unsigned long long u; float2 f; };

__device__ __forceinline__ void ffma2(unsigned long long& d,
                                      unsigned long long a,
                                      unsigned long long b) {
    asm("fma.rn.f32x2 %0, %1, %2, %0;" : "+l"(d) : "l"(a), "l"(b));
}
__device__ __forceinline__ void cp16(void* sdst, const void* gsrc) {
    unsigned sa = (unsigned)__cvta_generic_to_shared(sdst);
    asm volatile("cp.async.cg.shared.global [%0], [%1], 16;" :: "r"(sa), "l"(gsrc));
}
__device__ __forceinline__ void cp_commit() {
    asm volatile("cp.async.commit_group;" ::: "memory");
}
__device__ __forceinline__ void cp_wait1() {
    asm volatile("cp.async.wait_group 1;" ::: "memory");
}

// ---------------- 1) x transpose: tile 32 nodes x 8 batches ----------------
// smem 8.3KB/CTA (vs 33KB) -> 4x more resident CTAs -> latency actually hidden.
// blockIdx.x = node tile (32), blockIdx.y = batch tile (8).
__global__ __launch_bounds__(256) void transpose_kernel(const float* __restrict__ x) {
    __shared__ float s[8][260];     // [b_local][cl*8+i], +4 pad
    int c0 = blockIdx.x * 32;
    int b0 = blockIdx.y * 8;
    int t  = threadIdx.x;
    int nc = min(32, NN - c0);
    int nf4 = nc * 2;

    // read: coalesced along c within each batch row (512 f4 = 2 iters)
#pragma unroll
    for (int it = 0; it < 2; it++) {
        int id = it * 256 + t;
        int bl = id >> 6, f4 = id & 63;
        if (f4 < nf4) {
            float4 v = __ldg((const float4*)x + (long)(b0 + bl) * (XS / 4) + c0 * 2 + f4);
            *(float4*)&s[bl][f4 * 4] = v;
        }
    }
    __syncthreads();

    // write: 16 f4 per node (8 batches x 2) = 256B contiguous per node
#pragma unroll
    for (int it = 0; it < 2; it++) {
        int id = it * 256 + t;
        int cl = id >> 4, f4o = id & 15;
        if (cl < nc) {
            int bl = f4o >> 1;
            int i4 = (f4o & 1) * 4;
            float4 v = *(float4*)&s[bl][cl * 8 + i4];
            *((float4*)g_xc + (long)(c0 + cl) * 64 + (b0 + bl) * 2 + (f4o & 1)) = v;
        }
    }
    if (blockIdx.y == 0 && t < nc) g_counts[c0 + t] = 0;
}

// ---------------- 2) padded-bucket scatter ----------------
__global__ void scatter_kernel(const int* __restrict__ rows,
                               const int* __restrict__ cols) {
    int i = blockIdx.x * 256 + threadIdx.x;
    if (i < NE) {
        int r = __ldg(&rows[i]);
        int c = __ldg(&cols[i]);
        int p = atomicAdd(&g_counts[r], 1);
        if (p < MAXDEG)
            g_edge[(long)r * MAXDEG + p] = ((long long)i << 32) | (unsigned)c;
    }
}

// ---------------- 3) compute: WARP PER ROW, EDGE PAIRS (R11 config) ----------------
// lane = jp*8 + s.  Pair of edges per iter: 2KB x via cp.async one pair ahead,
// v transposed smem one pair ahead, descriptors int4 2 ahead.
__global__ __launch_bounds__(32, 28) void compute_kernel(
    const float* __restrict__ values,
    const float* __restrict__ bias,
    float* __restrict__ out)
{
    __shared__ __align__(16) float sx[2][2][256];   // [pairbuf][edge][1KB]
    __shared__ __align__(16) float vt[2][2][96];    // [pairbuf][edge][j*12+i]

    int lane = threadIdx.x;
    int r    = blockIdx.x;
    int jp   = lane >> 3;
    int s    = lane & 7;

    int n = min(g_counts[r], MAXDEG);
    const int4* eb4 = (const int4*)(g_edge + (long)r * MAXDEG); // {colA,permA,colB,permB}

    int f0 = lane * 2, f1 = f0 + 1;
    int st0 = (f0 & 7) * 12 + (f0 >> 3);
    int st1 = (f1 & 7) * 12 + (f1 >> 3);

    int j0off = (2 * jp) * 12 + (s & 1) * 4;
    int j1off = j0off + 12;

    unsigned long long acc[8][2];
#pragma unroll
    for (int q = 0; q < 8; q++) { acc[q][0] = 0ull; acc[q][1] = 0ull; }

    int P = (n + 1) >> 1;
    int4 e1;
    if (n > 0) {
        int4 e0 = __ldg(eb4);
        const float* xa = g_xc + (long)e0.x * 256;
        const float* xb = g_xc + (long)e0.z * 256;   // pad: stale-but-valid col
        cp16(&sx[0][0][lane * 4],        xa + lane * 4);
        cp16(&sx[0][0][(lane + 32) * 4], xa + (lane + 32) * 4);
        cp16(&sx[0][1][lane * 4],        xb + lane * 4);
        cp16(&sx[0][1][(lane + 32) * 4], xb + (lane + 32) * 4);
        cp_commit();
        float2 v0 = __ldcs((const float2*)(values + (long)e0.y * 64) + lane);
        float2 v1 = make_float2(0.0f, 0.0f);
        if (n > 1) v1 = __ldcs((const float2*)(values + (long)e0.w * 64) + lane);
        vt[0][0][st0] = v0.x; vt[0][0][st1] = v0.y;
        vt[0][1][st0] = v1.x; vt[0][1][st1] = v1.y;
        if (P > 1) e1 = __ldg(eb4 + 1);
    }

    for (int p = 0; p < P; p++) {
        bool more = (p + 1 < P);

        float2 van, vbn;
        if (more) {
            const float* xa = g_xc + (long)e1.x * 256;
            const float* xb = g_xc + (long)e1.z * 256;
            float* xd0 = &sx[(p + 1) & 1][0][0];
            float* xd1 = &sx[(p + 1) & 1][1][0];
            cp16(xd0 + lane * 4,        xa + lane * 4);
            cp16(xd0 + (lane + 32) * 4, xa + (lane + 32) * 4);
            cp16(xd1 + lane * 4,        xb + lane * 4);
            cp16(xd1 + (lane + 32) * 4, xb + (lane + 32) * 4);
            van = __ldcs((const float2*)(values + (long)e1.y * 64) + lane);
            vbn = make_float2(0.0f, 0.0f);
            if (2 * (p + 1) + 1 < n)
                vbn = __ldcs((const float2*)(values + (long)e1.w * 64) + lane);
        }
        cp_commit();
        int4 e2;
        if (p + 2 < P) e2 = __ldg(eb4 + p + 2);

        cp_wait1();
        __syncwarp();

#pragma unroll
        for (int e = 0; e < 2; e++) {
            const float* xs  = &sx[p & 1][e][0];
            const float* vtc = &vt[p & 1][e][0];

            F4 va, vb;
            va.f = *(const float4*)(vtc + j0off);
            vb.f = *(const float4*)(vtc + j1off);

            F4 x0, x1, x2, x3, x4, x5, x6, x7;
            x0.f = *((const float4*)xs + s);
            x1.f = *((const float4*)xs + s + 8);
            x2.f = *((const float4*)xs + s + 16);
            x3.f = *((const float4*)xs + s + 24);
            x4.f = *((const float4*)xs + s + 32);
            x5.f = *((const float4*)xs + s + 40);
            x6.f = *((const float4*)xs + s + 48);
            x7.f = *((const float4*)xs + s + 56);

            ffma2(acc[0][0], x0.u.x, va.u.x); ffma2(acc[0][0], x0.u.y, va.u.y);
            ffma2(acc[0][1], x0.u.x, vb.u.x); ffma2(acc[0][1], x0.u.y, vb.u.y);
            ffma2(acc[1][0], x1.u.x, va.u.x); ffma2(acc[1][0], x1.u.y, va.u.y);
            ffma2(acc[1][1], x1.u.x, vb.u.x); ffma2(acc[1][1], x1.u.y, vb.u.y);
            ffma2(acc[2][0], x2.u.x, va.u.x); ffma2(acc[2][0], x2.u.y, va.u.y);
            ffma2(acc[2][1], x2.u.x, vb.u.x); ffma2(acc[2][1], x2.u.y, vb.u.y);
            ffma2(acc[3][0], x3.u.x, va.u.x); ffma2(acc[3][0], x3.u.y, va.u.y);
            ffma2(acc[3][1], x3.u.x, vb.u.x); ffma2(acc[3][1], x3.u.y, vb.u.y);
            ffma2(acc[4][0], x4.u.x, va.u.x); ffma2(acc[4][0], x4.u.y, va.u.y);
            ffma2(acc[4][1], x4.u.x, vb.u.x); ffma2(acc[4][1], x4.u.y, vb.u.y);
            ffma2(acc[5][0], x5.u.x, va.u.x); ffma2(acc[5][0], x5.u.y, va.u.y);
            ffma2(acc[5][1], x5.u.x, vb.u.x); ffma2(acc[5][1], x5.u.y, vb.u.y);
            ffma2(acc[6][0], x6.u.x, va.u.x); ffma2(acc[6][0], x6.u.y, va.u.y);
            ffma2(acc[6][1], x6.u.x, vb.u.x); ffma2(acc[6][1], x6.u.y, vb.u.y);
            ffma2(acc[7][0], x7.u.x, va.u.x); ffma2(acc[7][0], x7.u.y, va.u.y);
            ffma2(acc[7][1], x7.u.x, vb.u.x); ffma2(acc[7][1], x7.u.y, vb.u.y);
        }

        if (more) {
            float* vd0 = &vt[(p + 1) & 1][0][0];
            float* vd1 = &vt[(p + 1) & 1][1][0];
            vd0[st0] = van.x; vd0[st1] = van.y;
            vd1[st0] = vbn.x; vd1[st1] = vbn.y;
            e1 = e2;
        }
    }

    // ---- epilogue: merge i-halves (lanes s, s^1), add bias, store ----
    int jw = s & 1;
    int b0 = s >> 1;
    int ob = r * 8 + 2 * jp + jw;
    float bb = __ldg(&bias[ob]);
#pragma unroll
    for (int q = 0; q < 8; q++) {
        U64F2 t0, t1;
        t0.u = acc[q][0];
        t1.u = acc[q][1];
        float v0 = t0.f.x + t0.f.y;
        float v1 = t1.f.x + t1.f.y;
        v0 += __shfl_xor_sync(0xffffffffu, v0, 1);
        v1 += __shfl_xor_sync(0xffffffffu, v1, 1);
        float vw = jw ? v1 : v0;
        out[(long)(4 * q + b0) * XS + ob] = vw + bb;
    }
}

// ---------------- launch ----------------
extern "C" void kernel_launch(void* const* d_in, const int* in_sizes, int n_in,
                              void* d_out, int out_size)
{
    const float* x      = (const float*)d_in[0];   // (32, 80000, 1)
    const float* values = (const float*)d_in[1];   // (320000, 8, 8)
    const float* bias   = (const float*)d_in[2];   // (80000,)
    const int*   idx    = (const int*)d_in[3];     // (2, 320000)
    float*       out    = (float*)d_out;

    const int* rows = idx;
    const int* cols = idx + NE;

    dim3 tgrid((NN + 31) / 32, NB / 8);
    transpose_kernel<<<tgrid, 256>>>(x);                     // launch 0
    scatter_kernel<<<(NE + 255) / 256, 256>>>(rows, cols);   // launch 1
    compute_kernel<<<NN, 32>>>(values, bias, out);           // launch 2 (idx 5 -> profiled)
}

// round 16
// speedup vs baseline: 1.0439x; 1.0439x over previous
#include <cuda_runtime.h>

#define NN 10000
#define NB 32
#define NE 320000
#define XS (NN*8)       // 80000 floats per batch
#define MAXDEG 128

// ---------------- device scratch ----------------
__device__ __align__(128) int       g_counts[NN];
__device__ __align__(128) long long g_edge[NN * MAXDEG];   // (perm<<32)|col
__device__ __align__(128) float     g_xc[NN * NB * 8];     // xc[c][b*8+i], 1KB/node

// ---------------- helpers ----------------
union F4 { float4 f; ulonglong2 u; };
union U64F2 { unsigned long long u; float2 f; };

__device__ __forceinline__ void ffma2(unsigned long long& d,
                                      unsigned long long a,
                                      unsigned long long b) {
    asm("fma.rn.f32x2 %0, %1, %2, %0;" : "+l"(d) : "l"(a), "l"(b));
}

// ---------------- 1) x transpose: tile 32 nodes x 8 batches (R15, measured good) ----
__global__ __launch_bounds__(256) void transpose_kernel(const float* __restrict__ x) {
    __shared__ float s[8][260];
    int c0 = blockIdx.x * 32;
    int b0 = blockIdx.y * 8;
    int t  = threadIdx.x;
    int nc = min(32, NN - c0);
    int nf4 = nc * 2;

#pragma unroll
    for (int it = 0; it < 2; it++) {
        int id = it * 256 + t;
        int bl = id >> 6, f4 = id & 63;
        if (f4 < nf4) {
            float4 v = __ldg((const float4*)x + (long)(b0 + bl) * (XS / 4) + c0 * 2 + f4);
            *(float4*)&s[bl][f4 * 4] = v;
        }
    }
    __syncthreads();

#pragma unroll
    for (int it = 0; it < 2; it++) {
        int id = it * 256 + t;
        int cl = id >> 4, f4o = id & 15;
        if (cl < nc) {
            int bl = f4o >> 1;
            int i4 = (f4o & 1) * 4;
            float4 v = *(float4*)&s[bl][cl * 8 + i4];
            *((float4*)g_xc + (long)(c0 + cl) * 64 + (b0 + bl) * 2 + (f4o & 1)) = v;
        }
    }
    if (blockIdx.y == 0 && t < nc) g_counts[c0 + t] = 0;
}

// ---------------- 2) padded-bucket scatter ----------------
__global__ void scatter_kernel(const int* __restrict__ rows,
                               const int* __restrict__ cols) {
    int i = blockIdx.x * 256 + threadIdx.x;
    if (i < NE) {
        int r = __ldg(&rows[i]);
        int c = __ldg(&cols[i]);
        int p = atomicAdd(&g_counts[r], 1);
        if (p < MAXDEG)
            g_edge[(long)r * MAXDEG + p] = ((long long)i << 32) | (unsigned)c;
    }
}

// ---------------- 3) compute: WARP PER ROW, HYBRID dataflow ----------------
// R12 work split: lane = bg*4 + ih*2 + jg; thread owns batches {bg+8t}, i-half ih,
// j's {4jg..4jg+3}.  x: 4 direct LDG.128/edge into registers, double-buffered ONE
// EDGE ahead (no x smem at all).  v: R12 pair-pipelined transposed smem.
__global__ __launch_bounds__(32, 20) void compute_kernel(
    const float* __restrict__ values,
    const float* __restrict__ bias,
    float* __restrict__ out)
{
    __shared__ __align__(16) float vt[2][2][80];    // [pairbuf][edge][ih*36 + j*4 + (i&3)]

    int lane = threadIdx.x;
    int r    = blockIdx.x;
    int bg   = lane >> 2;
    int ih   = (lane >> 1) & 1;
    int jg   = lane & 1;

    int n = min(g_counts[r], MAXDEG);
    const int4* eb4 = (const int4*)(g_edge + (long)r * MAXDEG); // {colA,permA,colB,permB}

    // v staging: lane stages v floats e0=2*lane, e1=e0+1 (linear = i*8+j)
    int e0f = 2 * lane, e1f = e0f + 1;
    int st0 = ((e0f >> 5) & 1) * 36 + (e0f & 7) * 4 + ((e0f >> 3) & 3);
    int st1 = ((e1f >> 5) & 1) * 36 + (e1f & 7) * 4 + ((e1f >> 3) & 3);

    int voff = ih * 36 + jg * 16;     // f4 [ih][j=jg*4]
    int xif  = 2 * bg + ih;           // x f4 index base (batch bg, i-half ih)

    unsigned long long acc[4][4];     // [t][jj]; halves = i-pair partials
#pragma unroll
    for (int t = 0; t < 4; t++)
#pragma unroll
        for (int jj = 0; jj < 4; jj++) acc[t][jj] = 0ull;

    F4 xA[4], xB[4];

    auto ldx = [&](F4* xr, int col) {
        const float4* xp = (const float4*)(g_xc + (long)col * 256) + xif;
        xr[0].f = __ldg(xp);
        xr[1].f = __ldg(xp + 16);
        xr[2].f = __ldg(xp + 32);
        xr[3].f = __ldg(xp + 48);
    };

    auto consume = [&](const F4* xr, const float* vtf) {
        F4 v0, v1, v2, v3;
        v0.f = *(const float4*)(vtf + voff);
        v1.f = *(const float4*)(vtf + voff + 4);
        v2.f = *(const float4*)(vtf + voff + 8);
        v3.f = *(const float4*)(vtf + voff + 12);
        ffma2(acc[0][0], xr[0].u.x, v0.u.x); ffma2(acc[0][0], xr[0].u.y, v0.u.y);
        ffma2(acc[0][1], xr[0].u.x, v1.u.x); ffma2(acc[0][1], xr[0].u.y, v1.u.y);
        ffma2(acc[0][2], xr[0].u.x, v2.u.x); ffma2(acc[0][2], xr[0].u.y, v2.u.y);
        ffma2(acc[0][3], xr[0].u.x, v3.u.x); ffma2(acc[0][3], xr[0].u.y, v3.u.y);
        ffma2(acc[1][0], xr[1].u.x, v0.u.x); ffma2(acc[1][0], xr[1].u.y, v0.u.y);
        ffma2(acc[1][1], xr[1].u.x, v1.u.x); ffma2(acc[1][1], xr[1].u.y, v1.u.y);
        ffma2(acc[1][2], xr[1].u.x, v2.u.x); ffma2(acc[1][2], xr[1].u.y, v2.u.y);
        ffma2(acc[1][3], xr[1].u.x, v3.u.x); ffma2(acc[1][3], xr[1].u.y, v3.u.y);
        ffma2(acc[2][0], xr[2].u.x, v0.u.x); ffma2(acc[2][0], xr[2].u.y, v0.u.y);
        ffma2(acc[2][1], xr[2].u.x, v1.u.x); ffma2(acc[2][1], xr[2].u.y, v1.u.y);
        ffma2(acc[2][2], xr[2].u.x, v2.u.x); ffma2(acc[2][2], xr[2].u.y, v2.u.y);
        ffma2(acc[2][3], xr[2].u.x, v3.u.x); ffma2(acc[2][3], xr[2].u.y, v3.u.y);
        ffma2(acc[3][0], xr[3].u.x, v0.u.x); ffma2(acc[3][0], xr[3].u.y, v0.u.y);
        ffma2(acc[3][1], xr[3].u.x, v1.u.x); ffma2(acc[3][1], xr[3].u.y, v1.u.y);
        ffma2(acc[3][2], xr[3].u.x, v2.u.x); ffma2(acc[3][2], xr[3].u.y, v2.u.y);
        ffma2(acc[3][3], xr[3].u.x, v3.u.x); ffma2(acc[3][3], xr[3].u.y, v3.u.y);
    };

    int P = (n + 1) >> 1;             // pairs (last may contain zero-padded edge)
    int4 e1;                          // descriptors for pair p+1
    if (n > 0) {
        int4 e0 = __ldg(eb4);
        ldx(xA, e0.x);                // x edge 0
        ldx(xB, e0.z);                // x edge 1 (pad: stale-but-valid col)
        float2 v0 = __ldcs((const float2*)(values + (long)e0.y * 64) + lane);
        float2 v1 = make_float2(0.0f, 0.0f);
        if (n > 1) v1 = __ldcs((const float2*)(values + (long)e0.w * 64) + lane);
        vt[0][0][st0] = v0.x; vt[0][0][st1] = v0.y;
        vt[0][1][st0] = v1.x; vt[0][1][st1] = v1.y;
        if (P > 1) e1 = __ldg(eb4 + 1);
    }

    for (int p = 0; p < P; p++) {
        bool more = (p + 1 < P);

        // v LDG for pair p+1 (STS deferred to bottom)
        float2 van, vbn;
        if (more) {
            van = __ldcs((const float2*)(values + (long)e1.y * 64) + lane);
            vbn = make_float2(0.0f, 0.0f);
            if (2 * (p + 1) + 1 < n)
                vbn = __ldcs((const float2*)(values + (long)e1.w * 64) + lane);
        }
        int4 e2;
        if (p + 2 < P) e2 = __ldg(eb4 + p + 2);

        __syncwarp();                 // vt[p&1] stores (from prev iter) visible

        const float* vt0 = &vt[p & 1][0][0];
        const float* vt1 = &vt[p & 1][1][0];

        consume(xA, vt0);             // edge 2p
        if (more) ldx(xA, e1.x);      // prefetch x edge 2p+2 (used next pair)
        consume(xB, vt1);             // edge 2p+1
        if (more) ldx(xB, e1.z);      // prefetch x edge 2p+3

        if (more) {
            float* vd0 = &vt[(p + 1) & 1][0][0];
            float* vd1 = &vt[(p + 1) & 1][1][0];
            vd0[st0] = van.x; vd0[st1] = van.y;
            vd1[st0] = vbn.x; vd1[st1] = vbn.y;
            e1 = e2;
        }
    }

    // ---- epilogue: sum i-pair halves, merge ih partner (lane^2), store ----
#pragma unroll
    for (int t = 0; t < 4; t++) {
        int b = bg + 8 * t;
#pragma unroll
        for (int jj = 0; jj < 4; jj++) {
            U64F2 u;
            u.u = acc[t][jj];
            float sp = u.f.x + u.f.y;
            sp += __shfl_xor_sync(0xffffffffu, sp, 2);
            if ((jj >> 1) == ih) {          // split the 4 jj stores across ih lanes
                int ob = r * 8 + jg * 4 + jj;
                out[(long)b * XS + ob] = sp + __ldg(&bias[ob]);
            }
        }
    }
}

// ---------------- launch ----------------
extern "C" void kernel_launch(void* const* d_in, const int* in_sizes, int n_in,
                              void* d_out, int out_size)
{
    const float* x      = (const float*)d_in[0];   // (32, 80000, 1)
    const float* values = (const float*)d_in[1];   // (320000, 8, 8)
    const float* bias   = (const float*)d_in[2];   // (80000,)
    const int*   idx    = (const int*)d_in[3];     // (2, 320000)
    float*       out    = (float*)d_out;

    const int* rows = idx;
    const int* cols = idx + NE;

    dim3 tgrid((NN + 31) / 32, NB / 8);
    transpose_kernel<<<tgrid, 256>>>(x);                     // launch 0
    scatter_kernel<<<(NE + 255) / 256, 256>>>(rows, cols);   // launch 1
    compute_kernel<<<NN, 32>>>(values, bias, out);           // launch 2 (idx 5 -> profiled)
}